// round 14
// baseline (speedup 1.0000x reference)
#include <cuda_runtime.h>

#define BATCH    8192
#define NT       512

// ---- SMEM layout (floats) ---- (R10 layout; H1 region now unused/dead)
#define OFF_XS   0
#define OFF_W    5056
#define OFF_A    9856
#define OFF_Z    19556
#define OFF_SML  25764
#define SMEM_FLOATS (OFF_SML + 464)

typedef unsigned long long u64;

__device__ __forceinline__ u64 pk2(float s) {
    u64 r; asm("mov.b64 %0, {%1, %1};" : "=l"(r) : "f"(s)); return r;
}
__device__ __forceinline__ void fma2(u64& c, u64 a, u64 b) {
    asm("fma.rn.f32x2 %0, %1, %2, %3;" : "=l"(c) : "l"(a), "l"(b), "l"(c));
}
__device__ __forceinline__ float2 upk(u64 v) {
    float2 f; asm("mov.b64 {%0, %1}, %2;" : "=f"(f.x), "=f"(f.y) : "l"(v)); return f;
}

__global__ __launch_bounds__(NT, 2)
void value_net_kernel(const float* __restrict__ state,
                      const float* __restrict__ t_w1, const float* __restrict__ t_b1,
                      const float* __restrict__ t_w2, const float* __restrict__ t_b2,
                      const float* __restrict__ w_a_g, const float* __restrict__ w1_g,
                      const float* __restrict__ w2_g,  const float* __restrict__ v_w1,
                      const float* __restrict__ v_b1,  const float* __restrict__ v_w2,
                      const float* __restrict__ v_b2,  float* __restrict__ out)
{
    extern __shared__ float sm[];
    float* Xs   = sm + OFF_XS;          // stride 52
    float* W    = sm + OFF_W;           // stride 100
    float* pp2  = sm + OFF_A - 2048;    // [32][64] vv partials
    float* A    = sm + OFF_A;           // stride 100 (rows 0-95 normalized; row 96 unnormalized)
    float* wa52 = sm + OFF_A;           // stride 52 (early)
    float* w1s  = sm + OFF_A + 2496;    // [48][64] (early)
    float* vw1s = sm + OFF_A + 104;     // [64][64] (epilogue)
    float* Z    = sm + OFF_Z;           // stride 64
    float* w2s  = sm + OFF_Z;           // [64][64] (epilogue)
    float* h50  = sm + OFF_SML;
    float* vv   = sm + OFF_SML + 320;
    float* feat = sm + OFF_SML + 384;
    float* part = sm + OFF_SML + 448;
    float* ps96 = sm + OFF_SML + 452;   // 4 row-96 partial sums

    const int tid = threadIdx.x;
    const int b   = blockIdx.x;
    const float* st = state + (size_t)b * 96 * 64;
    const float4 z4i = make_float4(0.f, 0.f, 0.f, 0.f);

    // ======== R0: loads + MLP stage 1 ========
    if (tid < 50) {
        float acc = t_b1[tid];
        #pragma unroll
        for (int k = 0; k < 16; k++) acc += st[k] * t_w1[k * 50 + tid];
        h50[tid] = fmaxf(acc, 0.f);
    }
    for (int t = tid; t < 2496; t += NT) {
        if (t < 1152) {
            int r = t / 12, c = t % 12;
            *(float4*)(Xs + (r + 1) * 52 + c * 4) =
                *(const float4*)(st + r * 64 + 16 + c * 4);
        } else if (t < 1728) {
            int u = t - 1152; int r = u / 12, c = u % 12;
            *(float4*)(wa52 + r * 52 + c * 4) = ((const float4*)w_a_g)[u];
        } else {
            int u = t - 1728;
            ((float4*)w1s)[u] = ((const float4*)w1_g)[u];
        }
    }
    __syncthreads();

    // ======== R0b: Z rows 1..96 + W m=4..99 || tail: MLP2 -> W m0..3, Z row 0 ========
    if (tid < 448) {
        if (tid < 192) {                     // Z: 8-row x 4-col, f32x2
            int n0 = 1 + (tid >> 4) * 8, j0 = (tid & 15) * 4;
            u64 acc[8][2] = {};
            #pragma unroll 3
            for (int k = 0; k < 48; k += 4) {
                ulonglong2 w0 = *(const ulonglong2*)(w1s + (k + 0) * 64 + j0);
                ulonglong2 w1 = *(const ulonglong2*)(w1s + (k + 1) * 64 + j0);
                ulonglong2 w2 = *(const ulonglong2*)(w1s + (k + 2) * 64 + j0);
                ulonglong2 w3 = *(const ulonglong2*)(w1s + (k + 3) * 64 + j0);
                #pragma unroll
                for (int r = 0; r < 8; r++) {
                    float4 xv = *(const float4*)(Xs + (n0 + r) * 52 + k);
                    u64 s0 = pk2(xv.x), s1 = pk2(xv.y), s2 = pk2(xv.z), s3 = pk2(xv.w);
                    fma2(acc[r][0], s0, w0.x); fma2(acc[r][1], s0, w0.y);
                    fma2(acc[r][0], s1, w1.x); fma2(acc[r][1], s1, w1.y);
                    fma2(acc[r][0], s2, w2.x); fma2(acc[r][1], s2, w2.y);
                    fma2(acc[r][0], s3, w3.x); fma2(acc[r][1], s3, w3.y);
                }
            }
            #pragma unroll
            for (int r = 0; r < 8; r++)
                *(ulonglong2*)(Z + (n0 + r) * 64 + j0) = make_ulonglong2(acc[r][0], acc[r][1]);
        } else if (tid < 384) {              // W rows k0+8c, cols m0..m0+3
            int u = tid - 192;
            int k0 = u & 7, m0 = 4 + (u >> 3) * 4;
            float4 acc[6] = {z4i, z4i, z4i, z4i, z4i, z4i};
            #pragma unroll 3
            for (int j = 0; j < 48; j += 4) {
                float4 x0 = *(const float4*)(Xs + (m0 + 0) * 52 + j);
                float4 x1 = *(const float4*)(Xs + (m0 + 1) * 52 + j);
                float4 x2 = *(const float4*)(Xs + (m0 + 2) * 52 + j);
                float4 x3 = *(const float4*)(Xs + (m0 + 3) * 52 + j);
                #pragma unroll
                for (int c = 0; c < 6; c++) {
                    float4 w = *(const float4*)(wa52 + (k0 + 8 * c) * 52 + j);
                    acc[c].x += w.x*x0.x + w.y*x0.y + w.z*x0.z + w.w*x0.w;
                    acc[c].y += w.x*x1.x + w.y*x1.y + w.z*x1.z + w.w*x1.w;
                    acc[c].z += w.x*x2.x + w.y*x2.y + w.z*x2.z + w.w*x2.w;
                    acc[c].w += w.x*x3.x + w.y*x3.y + w.z*x3.z + w.w*x3.w;
                }
            }
            #pragma unroll
            for (int c = 0; c < 6; c++)
                *(float4*)(W + (k0 + 8 * c) * 100 + m0) = acc[c];
        }
    } else {
        int j = tid - 448;
        if (j < 48) {                        // MLP stage 2 -> Xs row 0
            float acc = t_b2[j];
            #pragma unroll 5
            for (int k = 0; k < 50; k++) acc += h50[k] * t_w2[k * 48 + j];
            Xs[j] = fmaxf(acc, 0.f);
        }
        asm volatile("bar.sync 1, 64;" ::: "memory");
        if (j < 12) {                        // W rows j+12c, cols 0..3
            float4 acc[4] = {z4i, z4i, z4i, z4i};
            #pragma unroll 3
            for (int jj = 0; jj < 48; jj += 4) {
                float4 x0 = *(const float4*)(Xs + jj);
                float4 x1 = *(const float4*)(Xs + 52 + jj);
                float4 x2 = *(const float4*)(Xs + 104 + jj);
                float4 x3 = *(const float4*)(Xs + 156 + jj);
                #pragma unroll
                for (int c = 0; c < 4; c++) {
                    float4 w = *(const float4*)(wa52 + (j + 12 * c) * 52 + jj);
                    acc[c].x += w.x*x0.x + w.y*x0.y + w.z*x0.z + w.w*x0.w;
                    acc[c].y += w.x*x1.x + w.y*x1.y + w.z*x1.z + w.w*x1.w;
                    acc[c].z += w.x*x2.x + w.y*x2.y + w.z*x2.z + w.w*x2.w;
                    acc[c].w += w.x*x3.x + w.y*x3.y + w.z*x3.z + w.w*x3.w;
                }
            }
            #pragma unroll
            for (int c = 0; c < 4; c++)
                *(float4*)(W + (j + 12 * c) * 100) = acc[c];
        } else if (j < 28) {                 // Z row 0
            int j0 = (j - 12) * 4;
            float4 a = z4i;
            #pragma unroll 4
            for (int k = 0; k < 48; k++) {
                float4 w4 = *(const float4*)(w1s + k * 64 + j0);
                a.x += Xs[k]*w4.x; a.y += Xs[k]*w4.y; a.z += Xs[k]*w4.z; a.w += Xs[k]*w4.w;
            }
            *(float4*)(Z + j0) = a;
        }
    }
    __syncthreads();

    // ======== Scores + fused softmax: rows 0..95 (16 warps x 6 rows);
    //          row 96 split over warps 12-15 (unnormalized, deferred scale) ========
    {
        int warp = tid >> 5, lane = tid & 31;
        int m0 = ((lane < 25) ? lane : 24) * 4;
        int n0 = warp * 6;
        u64 acc[6][2] = {};
        #pragma unroll 3
        for (int k = 0; k < 48; k += 4) {
            ulonglong2 w0 = *(const ulonglong2*)(W + (k + 0) * 100 + m0);
            ulonglong2 w1 = *(const ulonglong2*)(W + (k + 1) * 100 + m0);
            ulonglong2 w2 = *(const ulonglong2*)(W + (k + 2) * 100 + m0);
            ulonglong2 w3 = *(const ulonglong2*)(W + (k + 3) * 100 + m0);
            #pragma unroll
            for (int r = 0; r < 6; r++) {
                float4 xv = *(const float4*)(Xs + (n0 + r) * 52 + k);
                u64 s0 = pk2(xv.x), s1 = pk2(xv.y), s2 = pk2(xv.z), s3 = pk2(xv.w);
                fma2(acc[r][0], s0, w0.x); fma2(acc[r][1], s0, w0.y);
                fma2(acc[r][0], s1, w1.x); fma2(acc[r][1], s1, w1.y);
                fma2(acc[r][0], s2, w2.x); fma2(acc[r][1], s2, w2.y);
                fma2(acc[r][0], s3, w3.x); fma2(acc[r][1], s3, w3.y);
            }
        }
        float e[6][4];
        float p[6];
        #pragma unroll
        for (int r = 0; r < 6; r++) {
            float2 lo = upk(acc[r][0]), hi = upk(acc[r][1]);
            e[r][0] = __expf(lo.x); e[r][1] = __expf(lo.y);
            e[r][2] = __expf(hi.x); e[r][3] = __expf(hi.y);
            p[r] = (lane < 24) ? (e[r][0] + e[r][1]) + (e[r][2] + e[r][3])
                               : ((lane == 24) ? e[r][0] : 0.f);
        }
        #pragma unroll
        for (int o = 16; o; o >>= 1) {
            #pragma unroll
            for (int r = 0; r < 6; r++) p[r] += __shfl_xor_sync(~0u, p[r], o);
        }
        if (lane < 25) {
            #pragma unroll
            for (int r = 0; r < 6; r++) {
                float iv = 1.f / p[r];
                *(float4*)(A + (n0 + r) * 100 + m0) =
                    make_float4(e[r][0] * iv, e[r][1] * iv, e[r][2] * iv, e[r][3] * iv);
            }
        }
        if (warp >= 12) {                    // row 96: quarter-sweeps, ~7 lanes each
            int wi = warp - 12;
            int tbase = (wi == 0) ? 0 : 7 + (wi - 1) * 6;
            int cnt   = (wi == 0) ? 7 : 6;
            bool act  = lane < cnt;
            int tile  = tbase + (act ? lane : 0);
            int m0r   = tile * 4;
            u64 b0 = 0, b1 = 0;
            #pragma unroll 3
            for (int k = 0; k < 48; k += 4) {
                ulonglong2 w0 = *(const ulonglong2*)(W + (k + 0) * 100 + m0r);
                ulonglong2 w1 = *(const ulonglong2*)(W + (k + 1) * 100 + m0r);
                ulonglong2 w2 = *(const ulonglong2*)(W + (k + 2) * 100 + m0r);
                ulonglong2 w3 = *(const ulonglong2*)(W + (k + 3) * 100 + m0r);
                float4 xv = *(const float4*)(Xs + 96 * 52 + k);
                u64 s0 = pk2(xv.x), s1 = pk2(xv.y), s2 = pk2(xv.z), s3 = pk2(xv.w);
                fma2(b0, s0, w0.x); fma2(b1, s0, w0.y);
                fma2(b0, s1, w1.x); fma2(b1, s1, w1.y);
                fma2(b0, s2, w2.x); fma2(b1, s2, w2.y);
                fma2(b0, s3, w3.x); fma2(b1, s3, w3.y);
            }
            float2 lo = upk(b0), hi = upk(b1);
            float e0 = __expf(lo.x), e1 = __expf(lo.y), e2 = __expf(hi.x), e3 = __expf(hi.y);
            float q = !act ? 0.f : ((tile == 24) ? e0 : (e0 + e1) + (e2 + e3));
            #pragma unroll
            for (int o = 16; o; o >>= 1) q += __shfl_xor_sync(~0u, q, o);
            if (lane == 0) ps96[wi] = q;
            if (act)
                *(float4*)(A + 96 * 100 + m0r) = make_float4(e0, e1, e2, e3);
        }
    }
    __syncthreads();

    // ======== h1 = relu(A @ Z) -> fused vv partials ONLY (H1 stores removed: dead) ========
    {
        int nt = tid >> 4, j0 = (tid & 15) * 4;
        int n0 = nt * 3;
        bool last = (nt == 31);
        u64 c0[2] = {}, c1[2] = {}, c2[2] = {}, c3[2] = {};
        for (int m = 0; m < 96; m += 4) {
            ulonglong2 z0 = *(const ulonglong2*)(Z + (m + 0) * 64 + j0);
            ulonglong2 z1 = *(const ulonglong2*)(Z + (m + 1) * 64 + j0);
            ulonglong2 z2 = *(const ulonglong2*)(Z + (m + 2) * 64 + j0);
            ulonglong2 z3 = *(const ulonglong2*)(Z + (m + 3) * 64 + j0);
            float4 a0 = *(const float4*)(A + (n0 + 0) * 100 + m);
            float4 a1 = *(const float4*)(A + (n0 + 1) * 100 + m);
            float4 a2 = *(const float4*)(A + (n0 + 2) * 100 + m);
            u64 p;
            p = pk2(a0.x); fma2(c0[0], p, z0.x); fma2(c0[1], p, z0.y);
            p = pk2(a0.y); fma2(c0[0], p, z1.x); fma2(c0[1], p, z1.y);
            p = pk2(a0.z); fma2(c0[0], p, z2.x); fma2(c0[1], p, z2.y);
            p = pk2(a0.w); fma2(c0[0], p, z3.x); fma2(c0[1], p, z3.y);
            p = pk2(a1.x); fma2(c1[0], p, z0.x); fma2(c1[1], p, z0.y);
            p = pk2(a1.y); fma2(c1[0], p, z1.x); fma2(c1[1], p, z1.y);
            p = pk2(a1.z); fma2(c1[0], p, z2.x); fma2(c1[1], p, z2.y);
            p = pk2(a1.w); fma2(c1[0], p, z3.x); fma2(c1[1], p, z3.y);
            p = pk2(a2.x); fma2(c2[0], p, z0.x); fma2(c2[1], p, z0.y);
            p = pk2(a2.y); fma2(c2[0], p, z1.x); fma2(c2[1], p, z1.y);
            p = pk2(a2.z); fma2(c2[0], p, z2.x); fma2(c2[1], p, z2.y);
            p = pk2(a2.w); fma2(c2[0], p, z3.x); fma2(c2[1], p, z3.y);
            if (last) {
                float4 a3 = *(const float4*)(A + 96 * 100 + m);   // unnormalized e
                p = pk2(a3.x); fma2(c3[0], p, z0.x); fma2(c3[1], p, z0.y);
                p = pk2(a3.y); fma2(c3[0], p, z1.x); fma2(c3[1], p, z1.y);
                p = pk2(a3.z); fma2(c3[0], p, z2.x); fma2(c3[1], p, z2.y);
                p = pk2(a3.w); fma2(c3[0], p, z3.x); fma2(c3[1], p, z3.y);
            }
        }
        {   // tail m = 96
            ulonglong2 zt = *(const ulonglong2*)(Z + 96 * 64 + j0);
            u64 p;
            p = pk2(A[(n0 + 0) * 100 + 96]); fma2(c0[0], p, zt.x); fma2(c0[1], p, zt.y);
            p = pk2(A[(n0 + 1) * 100 + 96]); fma2(c1[0], p, zt.x); fma2(c1[1], p, zt.y);
            p = pk2(A[(n0 + 2) * 100 + 96]); fma2(c2[0], p, zt.x); fma2(c2[1], p, zt.y);
            if (last) { p = pk2(A[96 * 100 + 96]); fma2(c3[0], p, zt.x); fma2(c3[1], p, zt.y); }
        }
        float2 l0 = upk(c0[0]), h0 = upk(c0[1]);
        float2 l1 = upk(c1[0]), h1v = upk(c1[1]);
        float2 l2 = upk(c2[0]), h2v = upk(c2[1]);
        float4 v0 = make_float4(fmaxf(l0.x,0.f), fmaxf(l0.y,0.f), fmaxf(h0.x,0.f), fmaxf(h0.y,0.f));
        float4 v1 = make_float4(fmaxf(l1.x,0.f), fmaxf(l1.y,0.f), fmaxf(h1v.x,0.f), fmaxf(h1v.y,0.f));
        float4 v2 = make_float4(fmaxf(l2.x,0.f), fmaxf(l2.y,0.f), fmaxf(h2v.x,0.f), fmaxf(h2v.y,0.f));
        // vv partials (A row 0 is normalized)
        float pa0 = A[n0 + 0], pa1 = A[n0 + 1], pa2 = A[n0 + 2];
        float4 pv;
        pv.x = pa0 * v0.x + pa1 * v1.x + pa2 * v2.x;
        pv.y = pa0 * v0.y + pa1 * v1.y + pa2 * v2.y;
        pv.z = pa0 * v0.z + pa1 * v1.z + pa2 * v2.z;
        pv.w = pa0 * v0.w + pa1 * v1.w + pa2 * v2.w;
        if (last) {
            // deferred row-96 normalization: h1[96] = iv96 * relu(e96 @ Z)
            float iv96 = 1.f / (ps96[0] + ps96[1] + ps96[2] + ps96[3]);
            float2 l3 = upk(c3[0]), h3 = upk(c3[1]);
            float4 v3 = make_float4(iv96*fmaxf(l3.x,0.f), iv96*fmaxf(l3.y,0.f),
                                    iv96*fmaxf(h3.x,0.f), iv96*fmaxf(h3.y,0.f));
            float pa3 = A[96];               // col 96 of row 0 (normalized)
            pv.x += pa3 * v3.x; pv.y += pa3 * v3.y;
            pv.z += pa3 * v3.z; pv.w += pa3 * v3.w;
        }
        *(float4*)(pp2 + nt * 64 + j0) = pv;
    }
    __syncthreads();

    // ======== Epilogue: reduce vv || load w2/v_w1 ========
    if (tid < 64) {
        float acc = 0.f;
        #pragma unroll 8
        for (int q = 0; q < 32; q++) acc += pp2[q * 64 + tid];
        vv[tid] = acc;
    } else if (tid >= 256) {
        int u = tid - 256;
        for (int i = u; i < 1024; i += 256) {
            ((float4*)w2s)[i]  = ((const float4*)w2_g)[i];
            ((float4*)vw1s)[i] = ((const float4*)v_w1)[i];
        }
    }
    __syncthreads();
    if (tid < 64) {
        float acc = 0.f;
        #pragma unroll 4
        for (int k = 0; k < 64; k++) acc += vv[k] * w2s[k * 64 + tid];
        feat[tid] = fmaxf(acc, 0.f);
    }
    __syncthreads();
    if (tid < 64) {
        float acc = v_b1[tid];
        #pragma unroll 4
        for (int k = 0; k < 64; k++) acc += feat[k] * vw1s[k * 64 + tid];
        float g = fmaxf(acc, 0.f);
        float p = g * v_w2[tid];
        #pragma unroll
        for (int o = 16; o; o >>= 1) p += __shfl_xor_sync(~0u, p, o);
        if ((tid & 31) == 0) part[tid >> 5] = p;
    }
    __syncthreads();
    if (tid == 0) out[b] = part[0] + part[1] + v_b2[0];
}

extern "C" void kernel_launch(void* const* d_in, const int* in_sizes, int n_in,
                              void* d_out, int out_size) {
    const float* state = (const float*)d_in[0];
    const float* t_w1  = (const float*)d_in[1];
    const float* t_b1  = (const float*)d_in[2];
    const float* t_w2  = (const float*)d_in[3];
    const float* t_b2  = (const float*)d_in[4];
    const float* w_a   = (const float*)d_in[5];
    const float* w1    = (const float*)d_in[6];
    const float* w2    = (const float*)d_in[7];
    const float* v_w1  = (const float*)d_in[8];
    const float* v_b1  = (const float*)d_in[9];
    const float* v_w2  = (const float*)d_in[10];
    const float* v_b2  = (const float*)d_in[11];
    float* out = (float*)d_out;

    const int smem_bytes = SMEM_FLOATS * sizeof(float);
    cudaFuncSetAttribute(value_net_kernel,
                         cudaFuncAttributeMaxDynamicSharedMemorySize, smem_bytes);
    value_net_kernel<<<BATCH, NT, smem_bytes>>>(
        state, t_w1, t_b1, t_w2, t_b2, w_a, w1, w2, v_w1, v_b1, v_w2, v_b2, out);
}

// round 15
// speedup vs baseline: 1.6632x; 1.6632x over previous
#include <cuda_runtime.h>

#define BATCH    8192
#define NT       512

// ---- SMEM layout (floats) ---- (R10 exact)
#define OFF_XS   0
#define OFF_W    5056
#define OFF_A    9856
#define OFF_Z    19556
#define OFF_SML  25764
#define SMEM_FLOATS (OFF_SML + 464)

typedef unsigned long long u64;

__device__ __forceinline__ u64 pk2(float s) {
    u64 r; asm("mov.b64 %0, {%1, %1};" : "=l"(r) : "f"(s)); return r;
}
__device__ __forceinline__ void fma2(u64& c, u64 a, u64 b) {
    asm("fma.rn.f32x2 %0, %1, %2, %3;" : "=l"(c) : "l"(a), "l"(b), "l"(c));
}
__device__ __forceinline__ float2 upk(u64 v) {
    float2 f; asm("mov.b64 {%0, %1}, %2;" : "=f"(f.x), "=f"(f.y) : "l"(v)); return f;
}

__global__ __launch_bounds__(NT, 2)
void value_net_kernel(const float* __restrict__ state,
                      const float* __restrict__ t_w1, const float* __restrict__ t_b1,
                      const float* __restrict__ t_w2, const float* __restrict__ t_b2,
                      const float* __restrict__ w_a_g, const float* __restrict__ w1_g,
                      const float* __restrict__ w2_g,  const float* __restrict__ v_w1,
                      const float* __restrict__ v_b1,  const float* __restrict__ v_w2,
                      const float* __restrict__ v_b2,  float* __restrict__ out)
{
    extern __shared__ float sm[];
    float* Xs   = sm + OFF_XS;          // stride 52
    float* H1   = sm + OFF_XS;          // stride 64 (after scores)
    float* W    = sm + OFF_W;           // stride 100
    float* pp2  = sm + OFF_A - 2048;    // [32][64] vv partials
    float* A    = sm + OFF_A;           // stride 100 (normalized softmax)
    float* wa52 = sm + OFF_A;           // stride 52 (early)
    float* w1s  = sm + OFF_A + 2496;    // [48][64] (early)
    float* vw1s = sm + OFF_A + 104;     // [64][64] (epilogue)
    float* Z    = sm + OFF_Z;           // stride 64
    float* w2s  = sm + OFF_Z;           // [64][64] (epilogue)
    float* h50  = sm + OFF_SML;
    float* vv   = sm + OFF_SML + 320;
    float* feat = sm + OFF_SML + 384;
    float* part = sm + OFF_SML + 448;

    const int tid = threadIdx.x;
    const int b   = blockIdx.x;
    const float* st = state + (size_t)b * 96 * 64;
    const float4 z4i = make_float4(0.f, 0.f, 0.f, 0.f);

    // ======== R0: loads + MLP stage 1 ========
    if (tid < 50) {
        float acc = t_b1[tid];
        #pragma unroll
        for (int k = 0; k < 16; k++) acc += st[k] * t_w1[k * 50 + tid];
        h50[tid] = fmaxf(acc, 0.f);
    }
    for (int t = tid; t < 2496; t += NT) {
        if (t < 1152) {
            int r = t / 12, c = t % 12;
            *(float4*)(Xs + (r + 1) * 52 + c * 4) =
                *(const float4*)(st + r * 64 + 16 + c * 4);
        } else if (t < 1728) {
            int u = t - 1152; int r = u / 12, c = u % 12;
            *(float4*)(wa52 + r * 52 + c * 4) = ((const float4*)w_a_g)[u];
        } else {
            int u = t - 1728;
            ((float4*)w1s)[u] = ((const float4*)w1_g)[u];
        }
    }
    __syncthreads();

    // ======== R0b: Z rows 1..96 + W m=4..99 || tail: MLP2 -> W m0..3, Z row 0 ========
    if (tid < 448) {
        if (tid < 192) {                     // Z: 8-row x 4-col, f32x2
            int n0 = 1 + (tid >> 4) * 8, j0 = (tid & 15) * 4;
            u64 acc[8][2] = {};
            #pragma unroll 3
            for (int k = 0; k < 48; k += 4) {
                ulonglong2 w0 = *(const ulonglong2*)(w1s + (k + 0) * 64 + j0);
                ulonglong2 w1 = *(const ulonglong2*)(w1s + (k + 1) * 64 + j0);
                ulonglong2 w2 = *(const ulonglong2*)(w1s + (k + 2) * 64 + j0);
                ulonglong2 w3 = *(const ulonglong2*)(w1s + (k + 3) * 64 + j0);
                #pragma unroll
                for (int r = 0; r < 8; r++) {
                    float4 xv = *(const float4*)(Xs + (n0 + r) * 52 + k);
                    u64 s0 = pk2(xv.x), s1 = pk2(xv.y), s2 = pk2(xv.z), s3 = pk2(xv.w);
                    fma2(acc[r][0], s0, w0.x); fma2(acc[r][1], s0, w0.y);
                    fma2(acc[r][0], s1, w1.x); fma2(acc[r][1], s1, w1.y);
                    fma2(acc[r][0], s2, w2.x); fma2(acc[r][1], s2, w2.y);
                    fma2(acc[r][0], s3, w3.x); fma2(acc[r][1], s3, w3.y);
                }
            }
            #pragma unroll
            for (int r = 0; r < 8; r++)
                *(ulonglong2*)(Z + (n0 + r) * 64 + j0) = make_ulonglong2(acc[r][0], acc[r][1]);
        } else if (tid < 384) {              // W rows k0+8c, cols m0..m0+3
            int u = tid - 192;
            int k0 = u & 7, m0 = 4 + (u >> 3) * 4;
            float4 acc[6] = {z4i, z4i, z4i, z4i, z4i, z4i};
            #pragma unroll 3
            for (int j = 0; j < 48; j += 4) {
                float4 x0 = *(const float4*)(Xs + (m0 + 0) * 52 + j);
                float4 x1 = *(const float4*)(Xs + (m0 + 1) * 52 + j);
                float4 x2 = *(const float4*)(Xs + (m0 + 2) * 52 + j);
                float4 x3 = *(const float4*)(Xs + (m0 + 3) * 52 + j);
                #pragma unroll
                for (int c = 0; c < 6; c++) {
                    float4 w = *(const float4*)(wa52 + (k0 + 8 * c) * 52 + j);
                    acc[c].x += w.x*x0.x + w.y*x0.y + w.z*x0.z + w.w*x0.w;
                    acc[c].y += w.x*x1.x + w.y*x1.y + w.z*x1.z + w.w*x1.w;
                    acc[c].z += w.x*x2.x + w.y*x2.y + w.z*x2.z + w.w*x2.w;
                    acc[c].w += w.x*x3.x + w.y*x3.y + w.z*x3.z + w.w*x3.w;
                }
            }
            #pragma unroll
            for (int c = 0; c < 6; c++)
                *(float4*)(W + (k0 + 8 * c) * 100 + m0) = acc[c];
        }
    } else {
        int j = tid - 448;
        if (j < 48) {                        // MLP stage 2 -> Xs row 0
            float acc = t_b2[j];
            #pragma unroll 5
            for (int k = 0; k < 50; k++) acc += h50[k] * t_w2[k * 48 + j];
            Xs[j] = fmaxf(acc, 0.f);
        }
        asm volatile("bar.sync 1, 64;" ::: "memory");
        if (j < 12) {                        // W rows j+12c, cols 0..3
            float4 acc[4] = {z4i, z4i, z4i, z4i};
            #pragma unroll 3
            for (int jj = 0; jj < 48; jj += 4) {
                float4 x0 = *(const float4*)(Xs + jj);
                float4 x1 = *(const float4*)(Xs + 52 + jj);
                float4 x2 = *(const float4*)(Xs + 104 + jj);
                float4 x3 = *(const float4*)(Xs + 156 + jj);
                #pragma unroll
                for (int c = 0; c < 4; c++) {
                    float4 w = *(const float4*)(wa52 + (j + 12 * c) * 52 + jj);
                    acc[c].x += w.x*x0.x + w.y*x0.y + w.z*x0.z + w.w*x0.w;
                    acc[c].y += w.x*x1.x + w.y*x1.y + w.z*x1.z + w.w*x1.w;
                    acc[c].z += w.x*x2.x + w.y*x2.y + w.z*x2.z + w.w*x2.w;
                    acc[c].w += w.x*x3.x + w.y*x3.y + w.z*x3.z + w.w*x3.w;
                }
            }
            #pragma unroll
            for (int c = 0; c < 4; c++)
                *(float4*)(W + (j + 12 * c) * 100) = acc[c];
        } else if (j < 28) {                 // Z row 0
            int j0 = (j - 12) * 4;
            float4 a = z4i;
            #pragma unroll 4
            for (int k = 0; k < 48; k++) {
                float4 w4 = *(const float4*)(w1s + k * 64 + j0);
                a.x += Xs[k]*w4.x; a.y += Xs[k]*w4.y; a.z += Xs[k]*w4.z; a.w += Xs[k]*w4.w;
            }
            *(float4*)(Z + j0) = a;
        }
    }
    __syncthreads();

    // ======== Scores + fused softmax: A = softmax(X @ W), 16 warps x 6 rows ========
    {
        int warp = tid >> 5, lane = tid & 31;
        int m0 = ((lane < 25) ? lane : 24) * 4;
        int n0 = warp * 6;
        u64 acc[6][2] = {};
        #pragma unroll 3
        for (int k = 0; k < 48; k += 4) {
            ulonglong2 w0 = *(const ulonglong2*)(W + (k + 0) * 100 + m0);
            ulonglong2 w1 = *(const ulonglong2*)(W + (k + 1) * 100 + m0);
            ulonglong2 w2 = *(const ulonglong2*)(W + (k + 2) * 100 + m0);
            ulonglong2 w3 = *(const ulonglong2*)(W + (k + 3) * 100 + m0);
            #pragma unroll
            for (int r = 0; r < 6; r++) {
                float4 xv = *(const float4*)(Xs + (n0 + r) * 52 + k);
                u64 s0 = pk2(xv.x), s1 = pk2(xv.y), s2 = pk2(xv.z), s3 = pk2(xv.w);
                fma2(acc[r][0], s0, w0.x); fma2(acc[r][1], s0, w0.y);
                fma2(acc[r][0], s1, w1.x); fma2(acc[r][1], s1, w1.y);
                fma2(acc[r][0], s2, w2.x); fma2(acc[r][1], s2, w2.y);
                fma2(acc[r][0], s3, w3.x); fma2(acc[r][1], s3, w3.y);
            }
        }
        float e[6][4];
        float p[6];
        #pragma unroll
        for (int r = 0; r < 6; r++) {
            float2 lo = upk(acc[r][0]), hi = upk(acc[r][1]);
            e[r][0] = __expf(lo.x); e[r][1] = __expf(lo.y);
            e[r][2] = __expf(hi.x); e[r][3] = __expf(hi.y);
            p[r] = (lane < 24) ? (e[r][0] + e[r][1]) + (e[r][2] + e[r][3])
                               : ((lane == 24) ? e[r][0] : 0.f);
        }
        #pragma unroll
        for (int o = 16; o; o >>= 1) {
            #pragma unroll
            for (int r = 0; r < 6; r++) p[r] += __shfl_xor_sync(~0u, p[r], o);
        }
        if (lane < 25) {
            #pragma unroll
            for (int r = 0; r < 6; r++) {
                float iv = 1.f / p[r];
                *(float4*)(A + (n0 + r) * 100 + m0) =
                    make_float4(e[r][0] * iv, e[r][1] * iv, e[r][2] * iv, e[r][3] * iv);
            }
        }
        if (warp == 15) {                    // row 96
            u64 b0 = 0, b1 = 0;
            #pragma unroll 3
            for (int k = 0; k < 48; k += 4) {
                ulonglong2 w0 = *(const ulonglong2*)(W + (k + 0) * 100 + m0);
                ulonglong2 w1 = *(const ulonglong2*)(W + (k + 1) * 100 + m0);
                ulonglong2 w2 = *(const ulonglong2*)(W + (k + 2) * 100 + m0);
                ulonglong2 w3 = *(const ulonglong2*)(W + (k + 3) * 100 + m0);
                float4 xv = *(const float4*)(Xs + 96 * 52 + k);
                u64 s0 = pk2(xv.x), s1 = pk2(xv.y), s2 = pk2(xv.z), s3 = pk2(xv.w);
                fma2(b0, s0, w0.x); fma2(b1, s0, w0.y);
                fma2(b0, s1, w1.x); fma2(b1, s1, w1.y);
                fma2(b0, s2, w2.x); fma2(b1, s2, w2.y);
                fma2(b0, s3, w3.x); fma2(b1, s3, w3.y);
            }
            float2 lo = upk(b0), hi = upk(b1);
            float e0 = __expf(lo.x), e1 = __expf(lo.y), e2 = __expf(hi.x), e3 = __expf(hi.y);
            float q = (lane < 24) ? (e0 + e1) + (e2 + e3) : ((lane == 24) ? e0 : 0.f);
            #pragma unroll
            for (int o = 16; o; o >>= 1) q += __shfl_xor_sync(~0u, q, o);
            if (lane < 25) {
                float iv = 1.f / q;
                *(float4*)(A + 96 * 100 + m0) =
                    make_float4(e0 * iv, e1 * iv, e2 * iv, e3 * iv);
            }
        }
    }
    __syncthreads();

    // ======== h1 = relu(A @ Z) + fused vv partials, 512 jobs ========
    {
        int nt = tid >> 4, j0 = (tid & 15) * 4;
        int n0 = nt * 3;
        bool last = (nt == 31);
        u64 c0[2] = {}, c1[2] = {}, c2[2] = {}, c3[2] = {};
        for (int m = 0; m < 96; m += 4) {
            ulonglong2 z0 = *(const ulonglong2*)(Z + (m + 0) * 64 + j0);
            ulonglong2 z1 = *(const ulonglong2*)(Z + (m + 1) * 64 + j0);
            ulonglong2 z2 = *(const ulonglong2*)(Z + (m + 2) * 64 + j0);
            ulonglong2 z3 = *(const ulonglong2*)(Z + (m + 3) * 64 + j0);
            float4 a0 = *(const float4*)(A + (n0 + 0) * 100 + m);
            float4 a1 = *(const float4*)(A + (n0 + 1) * 100 + m);
            float4 a2 = *(const float4*)(A + (n0 + 2) * 100 + m);
            u64 p;
            p = pk2(a0.x); fma2(c0[0], p, z0.x); fma2(c0[1], p, z0.y);
            p = pk2(a0.y); fma2(c0[0], p, z1.x); fma2(c0[1], p, z1.y);
            p = pk2(a0.z); fma2(c0[0], p, z2.x); fma2(c0[1], p, z2.y);
            p = pk2(a0.w); fma2(c0[0], p, z3.x); fma2(c0[1], p, z3.y);
            p = pk2(a1.x); fma2(c1[0], p, z0.x); fma2(c1[1], p, z0.y);
            p = pk2(a1.y); fma2(c1[0], p, z1.x); fma2(c1[1], p, z1.y);
            p = pk2(a1.z); fma2(c1[0], p, z2.x); fma2(c1[1], p, z2.y);
            p = pk2(a1.w); fma2(c1[0], p, z3.x); fma2(c1[1], p, z3.y);
            p = pk2(a2.x); fma2(c2[0], p, z0.x); fma2(c2[1], p, z0.y);
            p = pk2(a2.y); fma2(c2[0], p, z1.x); fma2(c2[1], p, z1.y);
            p = pk2(a2.z); fma2(c2[0], p, z2.x); fma2(c2[1], p, z2.y);
            p = pk2(a2.w); fma2(c2[0], p, z3.x); fma2(c2[1], p, z3.y);
            if (last) {
                float4 a3 = *(const float4*)(A + 96 * 100 + m);
                p = pk2(a3.x); fma2(c3[0], p, z0.x); fma2(c3[1], p, z0.y);
                p = pk2(a3.y); fma2(c3[0], p, z1.x); fma2(c3[1], p, z1.y);
                p = pk2(a3.z); fma2(c3[0], p, z2.x); fma2(c3[1], p, z2.y);
                p = pk2(a3.w); fma2(c3[0], p, z3.x); fma2(c3[1], p, z3.y);
            }
        }
        {   // tail m = 96
            ulonglong2 zt = *(const ulonglong2*)(Z + 96 * 64 + j0);
            u64 p;
            p = pk2(A[(n0 + 0) * 100 + 96]); fma2(c0[0], p, zt.x); fma2(c0[1], p, zt.y);
            p = pk2(A[(n0 + 1) * 100 + 96]); fma2(c1[0], p, zt.x); fma2(c1[1], p, zt.y);
            p = pk2(A[(n0 + 2) * 100 + 96]); fma2(c2[0], p, zt.x); fma2(c2[1], p, zt.y);
            if (last) { p = pk2(A[96 * 100 + 96]); fma2(c3[0], p, zt.x); fma2(c3[1], p, zt.y); }
        }
        float2 l0 = upk(c0[0]), h0 = upk(c0[1]);
        float2 l1 = upk(c1[0]), h1v = upk(c1[1]);
        float2 l2 = upk(c2[0]), h2v = upk(c2[1]);
        float4 v0 = make_float4(fmaxf(l0.x,0.f), fmaxf(l0.y,0.f), fmaxf(h0.x,0.f), fmaxf(h0.y,0.f));
        float4 v1 = make_float4(fmaxf(l1.x,0.f), fmaxf(l1.y,0.f), fmaxf(h1v.x,0.f), fmaxf(h1v.y,0.f));
        float4 v2 = make_float4(fmaxf(l2.x,0.f), fmaxf(l2.y,0.f), fmaxf(h2v.x,0.f), fmaxf(h2v.y,0.f));
        *(float4*)(H1 + (n0 + 0) * 64 + j0) = v0;
        *(float4*)(H1 + (n0 + 1) * 64 + j0) = v1;
        *(float4*)(H1 + (n0 + 2) * 64 + j0) = v2;
        float pa0 = A[n0 + 0], pa1 = A[n0 + 1], pa2 = A[n0 + 2];
        float4 pv;
        pv.x = pa0 * v0.x + pa1 * v1.x + pa2 * v2.x;
        pv.y = pa0 * v0.y + pa1 * v1.y + pa2 * v2.y;
        pv.z = pa0 * v0.z + pa1 * v1.z + pa2 * v2.z;
        pv.w = pa0 * v0.w + pa1 * v1.w + pa2 * v2.w;
        if (last) {
            float2 l3 = upk(c3[0]), h3 = upk(c3[1]);
            float4 v3 = make_float4(fmaxf(l3.x,0.f), fmaxf(l3.y,0.f), fmaxf(h3.x,0.f), fmaxf(h3.y,0.f));
            *(float4*)(H1 + 96 * 64 + j0) = v3;
            float pa3 = A[96];
            pv.x += pa3 * v3.x; pv.y += pa3 * v3.y; pv.z += pa3 * v3.z; pv.w += pa3 * v3.w;
        }
        *(float4*)(pp2 + nt * 64 + j0) = pv;
    }
    __syncthreads();

    // ======== Epilogue: reduce vv || load w2/v_w1 ========
    if (tid < 64) {
        float acc = 0.f;
        #pragma unroll 8
        for (int q = 0; q < 32; q++) acc += pp2[q * 64 + tid];
        vv[tid] = acc;
    } else if (tid >= 256) {
        int u = tid - 256;
        for (int i = u; i < 1024; i += 256) {
            ((float4*)w2s)[i]  = ((const float4*)w2_g)[i];
            ((float4*)vw1s)[i] = ((const float4*)v_w1)[i];
        }
    }
    __syncthreads();
    if (tid < 64) {
        float acc = 0.f;
        #pragma unroll 4
        for (int k = 0; k < 64; k++) acc += vv[k] * w2s[k * 64 + tid];
        feat[tid] = fmaxf(acc, 0.f);
    }
    __syncthreads();
    if (tid < 64) {
        float acc = v_b1[tid];
        #pragma unroll 4
        for (int k = 0; k < 64; k++) acc += feat[k] * vw1s[k * 64 + tid];
        float g = fmaxf(acc, 0.f);
        float p = g * v_w2[tid];
        #pragma unroll
        for (int o = 16; o; o >>= 1) p += __shfl_xor_sync(~0u, p, o);
        if ((tid & 31) == 0) part[tid >> 5] = p;
    }
    __syncthreads();
    if (tid == 0) out[b] = part[0] + part[1] + v_b2[0];
}

extern "C" void kernel_launch(void* const* d_in, const int* in_sizes, int n_in,
                              void* d_out, int out_size) {
    const float* state = (const float*)d_in[0];
    const float* t_w1  = (const float*)d_in[1];
    const float* t_b1  = (const float*)d_in[2];
    const float* t_w2  = (const float*)d_in[3];
    const float* t_b2  = (const float*)d_in[4];
    const float* w_a   = (const float*)d_in[5];
    const float* w1    = (const float*)d_in[6];
    const float* w2    = (const float*)d_in[7];
    const float* v_w1  = (const float*)d_in[8];
    const float* v_b1  = (const float*)d_in[9];
    const float* v_w2  = (const float*)d_in[10];
    const float* v_b2  = (const float*)d_in[11];
    float* out = (float*)d_out;

    const int smem_bytes = SMEM_FLOATS * sizeof(float);
    cudaFuncSetAttribute(value_net_kernel,
                         cudaFuncAttributeMaxDynamicSharedMemorySize, smem_bytes);
    value_net_kernel<<<BATCH, NT, smem_bytes>>>(
        state, t_w1, t_b1, t_w2, t_b2, w_a, w1, w2, v_w1, v_b1, v_w2, v_b2, out);
}

// round 16
// speedup vs baseline: 1.6790x; 1.0095x over previous
#include <cuda_runtime.h>

#define BATCH    8192
#define NT       512

// ---- SMEM layout (floats) ---- (R10 exact)
#define OFF_XS   0
#define OFF_W    5056
#define OFF_A    9856
#define OFF_Z    19556
#define OFF_SML  25764
#define SMEM_FLOATS (OFF_SML + 464)

typedef unsigned long long u64;

__device__ __forceinline__ u64 pk2(float s) {
    u64 r; asm("mov.b64 %0, {%1, %1};" : "=l"(r) : "f"(s)); return r;
}
__device__ __forceinline__ void fma2(u64& c, u64 a, u64 b) {
    asm("fma.rn.f32x2 %0, %1, %2, %3;" : "=l"(c) : "l"(a), "l"(b), "l"(c));
}
__device__ __forceinline__ float2 upk(u64 v) {
    float2 f; asm("mov.b64 {%0, %1}, %2;" : "=f"(f.x), "=f"(f.y) : "l"(v)); return f;
}

__global__ __launch_bounds__(NT, 2)
void value_net_kernel(const float* __restrict__ state,
                      const float* __restrict__ t_w1, const float* __restrict__ t_b1,
                      const float* __restrict__ t_w2, const float* __restrict__ t_b2,
                      const float* __restrict__ w_a_g, const float* __restrict__ w1_g,
                      const float* __restrict__ w2_g,  const float* __restrict__ v_w1,
                      const float* __restrict__ v_b1,  const float* __restrict__ v_w2,
                      const float* __restrict__ v_b2,  float* __restrict__ out)
{
    extern __shared__ float sm[];
    float* Xs   = sm + OFF_XS;          // stride 52
    float* H1   = sm + OFF_XS;          // stride 64 (after scores)
    float* W    = sm + OFF_W;           // stride 100
    float* pp2  = sm + OFF_A - 2048;    // [32][64] vv partials
    float* A    = sm + OFF_A;           // stride 100 (normalized softmax)
    float* wa52 = sm + OFF_A;           // stride 52 (early)
    float* w1s  = sm + OFF_A + 2496;    // [48][64] (early)
    float* vw1s = sm + OFF_A + 104;     // [64][64] (epilogue)
    float* Z    = sm + OFF_Z;           // stride 64
    float* w2s  = sm + OFF_Z;           // [64][64] (epilogue)
    float* h50  = sm + OFF_SML;
    float* vv   = sm + OFF_SML + 320;
    float* feat = sm + OFF_SML + 384;
    float* part = sm + OFF_SML + 448;

    const int tid = threadIdx.x;
    const int b   = blockIdx.x;
    const float* st = state + (size_t)b * 96 * 64;
    const float4 z4i = make_float4(0.f, 0.f, 0.f, 0.f);

    // ======== R0: loads + MLP stage 1 ========
    if (tid < 50) {
        float acc = t_b1[tid];
        #pragma unroll
        for (int k = 0; k < 16; k++) acc += st[k] * t_w1[k * 50 + tid];
        h50[tid] = fmaxf(acc, 0.f);
    }
    for (int t = tid; t < 2496; t += NT) {
        if (t < 1152) {
            int r = t / 12, c = t % 12;
            *(float4*)(Xs + (r + 1) * 52 + c * 4) =
                *(const float4*)(st + r * 64 + 16 + c * 4);
        } else if (t < 1728) {
            int u = t - 1152; int r = u / 12, c = u % 12;
            *(float4*)(wa52 + r * 52 + c * 4) = ((const float4*)w_a_g)[u];
        } else {
            int u = t - 1728;
            ((float4*)w1s)[u] = ((const float4*)w1_g)[u];
        }
    }
    __syncthreads();

    // ======== R0b: Z rows 1..96 (256 jobs, 6-row) + W m=4..99 (192 jobs)
    //          -> 448 equal 1152-MAC jobs on 448 threads, zero stragglers
    //          || tail 448+: MLP2 -> W m0..3, Z row 0 ========
    if (tid < 448) {
        if (tid < 256) {                     // Z: 6-row x 4-col, f32x2
            int n0 = 1 + (tid >> 4) * 6, j0 = (tid & 15) * 4;
            u64 acc[6][2] = {};
            #pragma unroll 3
            for (int k = 0; k < 48; k += 4) {
                ulonglong2 w0 = *(const ulonglong2*)(w1s + (k + 0) * 64 + j0);
                ulonglong2 w1 = *(const ulonglong2*)(w1s + (k + 1) * 64 + j0);
                ulonglong2 w2 = *(const ulonglong2*)(w1s + (k + 2) * 64 + j0);
                ulonglong2 w3 = *(const ulonglong2*)(w1s + (k + 3) * 64 + j0);
                #pragma unroll
                for (int r = 0; r < 6; r++) {
                    float4 xv = *(const float4*)(Xs + (n0 + r) * 52 + k);
                    u64 s0 = pk2(xv.x), s1 = pk2(xv.y), s2 = pk2(xv.z), s3 = pk2(xv.w);
                    fma2(acc[r][0], s0, w0.x); fma2(acc[r][1], s0, w0.y);
                    fma2(acc[r][0], s1, w1.x); fma2(acc[r][1], s1, w1.y);
                    fma2(acc[r][0], s2, w2.x); fma2(acc[r][1], s2, w2.y);
                    fma2(acc[r][0], s3, w3.x); fma2(acc[r][1], s3, w3.y);
                }
            }
            #pragma unroll
            for (int r = 0; r < 6; r++)
                *(ulonglong2*)(Z + (n0 + r) * 64 + j0) = make_ulonglong2(acc[r][0], acc[r][1]);
        } else {                             // W rows k0+8c, cols m0..m0+3
            int u = tid - 256;
            int k0 = u & 7, m0 = 4 + (u >> 3) * 4;
            float4 acc[6] = {z4i, z4i, z4i, z4i, z4i, z4i};
            #pragma unroll 3
            for (int j = 0; j < 48; j += 4) {
                float4 x0 = *(const float4*)(Xs + (m0 + 0) * 52 + j);
                float4 x1 = *(const float4*)(Xs + (m0 + 1) * 52 + j);
                float4 x2 = *(const float4*)(Xs + (m0 + 2) * 52 + j);
                float4 x3 = *(const float4*)(Xs + (m0 + 3) * 52 + j);
                #pragma unroll
                for (int c = 0; c < 6; c++) {
                    float4 w = *(const float4*)(wa52 + (k0 + 8 * c) * 52 + j);
                    acc[c].x += w.x*x0.x + w.y*x0.y + w.z*x0.z + w.w*x0.w;
                    acc[c].y += w.x*x1.x + w.y*x1.y + w.z*x1.z + w.w*x1.w;
                    acc[c].z += w.x*x2.x + w.y*x2.y + w.z*x2.z + w.w*x2.w;
                    acc[c].w += w.x*x3.x + w.y*x3.y + w.z*x3.z + w.w*x3.w;
                }
            }
            #pragma unroll
            for (int c = 0; c < 6; c++)
                *(float4*)(W + (k0 + 8 * c) * 100 + m0) = acc[c];
        }
    } else {
        int j = tid - 448;
        if (j < 48) {                        // MLP stage 2 -> Xs row 0
            float acc = t_b2[j];
            #pragma unroll 5
            for (int k = 0; k < 50; k++) acc += h50[k] * t_w2[k * 48 + j];
            Xs[j] = fmaxf(acc, 0.f);
        }
        asm volatile("bar.sync 1, 64;" ::: "memory");
        if (j < 12) {                        // W rows j+12c, cols 0..3
            float4 acc[4] = {z4i, z4i, z4i, z4i};
            #pragma unroll 3
            for (int jj = 0; jj < 48; jj += 4) {
                float4 x0 = *(const float4*)(Xs + jj);
                float4 x1 = *(const float4*)(Xs + 52 + jj);
                float4 x2 = *(const float4*)(Xs + 104 + jj);
                float4 x3 = *(const float4*)(Xs + 156 + jj);
                #pragma unroll
                for (int c = 0; c < 4; c++) {
                    float4 w = *(const float4*)(wa52 + (j + 12 * c) * 52 + jj);
                    acc[c].x += w.x*x0.x + w.y*x0.y + w.z*x0.z + w.w*x0.w;
                    acc[c].y += w.x*x1.x + w.y*x1.y + w.z*x1.z + w.w*x1.w;
                    acc[c].z += w.x*x2.x + w.y*x2.y + w.z*x2.z + w.w*x2.w;
                    acc[c].w += w.x*x3.x + w.y*x3.y + w.z*x3.z + w.w*x3.w;
                }
            }
            #pragma unroll
            for (int c = 0; c < 4; c++)
                *(float4*)(W + (j + 12 * c) * 100) = acc[c];
        } else if (j < 28) {                 // Z row 0
            int j0 = (j - 12) * 4;
            float4 a = z4i;
            #pragma unroll 4
            for (int k = 0; k < 48; k++) {
                float4 w4 = *(const float4*)(w1s + k * 64 + j0);
                a.x += Xs[k]*w4.x; a.y += Xs[k]*w4.y; a.z += Xs[k]*w4.z; a.w += Xs[k]*w4.w;
            }
            *(float4*)(Z + j0) = a;
        }
    }
    __syncthreads();

    // ======== Scores + fused softmax: A = softmax(X @ W), 16 warps x 6 rows ========
    {
        int warp = tid >> 5, lane = tid & 31;
        int m0 = ((lane < 25) ? lane : 24) * 4;
        int n0 = warp * 6;
        u64 acc[6][2] = {};
        #pragma unroll 3
        for (int k = 0; k < 48; k += 4) {
            ulonglong2 w0 = *(const ulonglong2*)(W + (k + 0) * 100 + m0);
            ulonglong2 w1 = *(const ulonglong2*)(W + (k + 1) * 100 + m0);
            ulonglong2 w2 = *(const ulonglong2*)(W + (k + 2) * 100 + m0);
            ulonglong2 w3 = *(const ulonglong2*)(W + (k + 3) * 100 + m0);
            #pragma unroll
            for (int r = 0; r < 6; r++) {
                float4 xv = *(const float4*)(Xs + (n0 + r) * 52 + k);
                u64 s0 = pk2(xv.x), s1 = pk2(xv.y), s2 = pk2(xv.z), s3 = pk2(xv.w);
                fma2(acc[r][0], s0, w0.x); fma2(acc[r][1], s0, w0.y);
                fma2(acc[r][0], s1, w1.x); fma2(acc[r][1], s1, w1.y);
                fma2(acc[r][0], s2, w2.x); fma2(acc[r][1], s2, w2.y);
                fma2(acc[r][0], s3, w3.x); fma2(acc[r][1], s3, w3.y);
            }
        }
        float e[6][4];
        float p[6];
        #pragma unroll
        for (int r = 0; r < 6; r++) {
            float2 lo = upk(acc[r][0]), hi = upk(acc[r][1]);
            e[r][0] = __expf(lo.x); e[r][1] = __expf(lo.y);
            e[r][2] = __expf(hi.x); e[r][3] = __expf(hi.y);
            p[r] = (lane < 24) ? (e[r][0] + e[r][1]) + (e[r][2] + e[r][3])
                               : ((lane == 24) ? e[r][0] : 0.f);
        }
        #pragma unroll
        for (int o = 16; o; o >>= 1) {
            #pragma unroll
            for (int r = 0; r < 6; r++) p[r] += __shfl_xor_sync(~0u, p[r], o);
        }
        if (lane < 25) {
            #pragma unroll
            for (int r = 0; r < 6; r++) {
                float iv = 1.f / p[r];
                *(float4*)(A + (n0 + r) * 100 + m0) =
                    make_float4(e[r][0] * iv, e[r][1] * iv, e[r][2] * iv, e[r][3] * iv);
            }
        }
        if (warp == 15) {                    // row 96
            u64 b0 = 0, b1 = 0;
            #pragma unroll 3
            for (int k = 0; k < 48; k += 4) {
                ulonglong2 w0 = *(const ulonglong2*)(W + (k + 0) * 100 + m0);
                ulonglong2 w1 = *(const ulonglong2*)(W + (k + 1) * 100 + m0);
                ulonglong2 w2 = *(const ulonglong2*)(W + (k + 2) * 100 + m0);
                ulonglong2 w3 = *(const ulonglong2*)(W + (k + 3) * 100 + m0);
                float4 xv = *(const float4*)(Xs + 96 * 52 + k);
                u64 s0 = pk2(xv.x), s1 = pk2(xv.y), s2 = pk2(xv.z), s3 = pk2(xv.w);
                fma2(b0, s0, w0.x); fma2(b1, s0, w0.y);
                fma2(b0, s1, w1.x); fma2(b1, s1, w1.y);
                fma2(b0, s2, w2.x); fma2(b1, s2, w2.y);
                fma2(b0, s3, w3.x); fma2(b1, s3, w3.y);
            }
            float2 lo = upk(b0), hi = upk(b1);
            float e0 = __expf(lo.x), e1 = __expf(lo.y), e2 = __expf(hi.x), e3 = __expf(hi.y);
            float q = (lane < 24) ? (e0 + e1) + (e2 + e3) : ((lane == 24) ? e0 : 0.f);
            #pragma unroll
            for (int o = 16; o; o >>= 1) q += __shfl_xor_sync(~0u, q, o);
            if (lane < 25) {
                float iv = 1.f / q;
                *(float4*)(A + 96 * 100 + m0) =
                    make_float4(e0 * iv, e1 * iv, e2 * iv, e3 * iv);
            }
        }
    }
    __syncthreads();

    // ======== h1 = relu(A @ Z) + fused vv partials, 512 jobs ========
    {
        int nt = tid >> 4, j0 = (tid & 15) * 4;
        int n0 = nt * 3;
        bool last = (nt == 31);
        u64 c0[2] = {}, c1[2] = {}, c2[2] = {}, c3[2] = {};
        for (int m = 0; m < 96; m += 4) {
            ulonglong2 z0 = *(const ulonglong2*)(Z + (m + 0) * 64 + j0);
            ulonglong2 z1 = *(const ulonglong2*)(Z + (m + 1) * 64 + j0);
            ulonglong2 z2 = *(const ulonglong2*)(Z + (m + 2) * 64 + j0);
            ulonglong2 z3 = *(const ulonglong2*)(Z + (m + 3) * 64 + j0);
            float4 a0 = *(const float4*)(A + (n0 + 0) * 100 + m);
            float4 a1 = *(const float4*)(A + (n0 + 1) * 100 + m);
            float4 a2 = *(const float4*)(A + (n0 + 2) * 100 + m);
            u64 p;
            p = pk2(a0.x); fma2(c0[0], p, z0.x); fma2(c0[1], p, z0.y);
            p = pk2(a0.y); fma2(c0[0], p, z1.x); fma2(c0[1], p, z1.y);
            p = pk2(a0.z); fma2(c0[0], p, z2.x); fma2(c0[1], p, z2.y);
            p = pk2(a0.w); fma2(c0[0], p, z3.x); fma2(c0[1], p, z3.y);
            p = pk2(a1.x); fma2(c1[0], p, z0.x); fma2(c1[1], p, z0.y);
            p = pk2(a1.y); fma2(c1[0], p, z1.x); fma2(c1[1], p, z1.y);
            p = pk2(a1.z); fma2(c1[0], p, z2.x); fma2(c1[1], p, z2.y);
            p = pk2(a1.w); fma2(c1[0], p, z3.x); fma2(c1[1], p, z3.y);
            p = pk2(a2.x); fma2(c2[0], p, z0.x); fma2(c2[1], p, z0.y);
            p = pk2(a2.y); fma2(c2[0], p, z1.x); fma2(c2[1], p, z1.y);
            p = pk2(a2.z); fma2(c2[0], p, z2.x); fma2(c2[1], p, z2.y);
            p = pk2(a2.w); fma2(c2[0], p, z3.x); fma2(c2[1], p, z3.y);
            if (last) {
                float4 a3 = *(const float4*)(A + 96 * 100 + m);
                p = pk2(a3.x); fma2(c3[0], p, z0.x); fma2(c3[1], p, z0.y);
                p = pk2(a3.y); fma2(c3[0], p, z1.x); fma2(c3[1], p, z1.y);
                p = pk2(a3.z); fma2(c3[0], p, z2.x); fma2(c3[1], p, z2.y);
                p = pk2(a3.w); fma2(c3[0], p, z3.x); fma2(c3[1], p, z3.y);
            }
        }
        {   // tail m = 96
            ulonglong2 zt = *(const ulonglong2*)(Z + 96 * 64 + j0);
            u64 p;
            p = pk2(A[(n0 + 0) * 100 + 96]); fma2(c0[0], p, zt.x); fma2(c0[1], p, zt.y);
            p = pk2(A[(n0 + 1) * 100 + 96]); fma2(c1[0], p, zt.x); fma2(c1[1], p, zt.y);
            p = pk2(A[(n0 + 2) * 100 + 96]); fma2(c2[0], p, zt.x); fma2(c2[1], p, zt.y);
            if (last) { p = pk2(A[96 * 100 + 96]); fma2(c3[0], p, zt.x); fma2(c3[1], p, zt.y); }
        }
        float2 l0 = upk(c0[0]), h0 = upk(c0[1]);
        float2 l1 = upk(c1[0]), h1v = upk(c1[1]);
        float2 l2 = upk(c2[0]), h2v = upk(c2[1]);
        float4 v0 = make_float4(fmaxf(l0.x,0.f), fmaxf(l0.y,0.f), fmaxf(h0.x,0.f), fmaxf(h0.y,0.f));
        float4 v1 = make_float4(fmaxf(l1.x,0.f), fmaxf(l1.y,0.f), fmaxf(h1v.x,0.f), fmaxf(h1v.y,0.f));
        float4 v2 = make_float4(fmaxf(l2.x,0.f), fmaxf(l2.y,0.f), fmaxf(h2v.x,0.f), fmaxf(h2v.y,0.f));
        *(float4*)(H1 + (n0 + 0) * 64 + j0) = v0;
        *(float4*)(H1 + (n0 + 1) * 64 + j0) = v1;
        *(float4*)(H1 + (n0 + 2) * 64 + j0) = v2;
        float pa0 = A[n0 + 0], pa1 = A[n0 + 1], pa2 = A[n0 + 2];
        float4 pv;
        pv.x = pa0 * v0.x + pa1 * v1.x + pa2 * v2.x;
        pv.y = pa0 * v0.y + pa1 * v1.y + pa2 * v2.y;
        pv.z = pa0 * v0.z + pa1 * v1.z + pa2 * v2.z;
        pv.w = pa0 * v0.w + pa1 * v1.w + pa2 * v2.w;
        if (last) {
            float2 l3 = upk(c3[0]), h3 = upk(c3[1]);
            float4 v3 = make_float4(fmaxf(l3.x,0.f), fmaxf(l3.y,0.f), fmaxf(h3.x,0.f), fmaxf(h3.y,0.f));
            *(float4*)(H1 + 96 * 64 + j0) = v3;
            float pa3 = A[96];
            pv.x += pa3 * v3.x; pv.y += pa3 * v3.y; pv.z += pa3 * v3.z; pv.w += pa3 * v3.w;
        }
        *(float4*)(pp2 + nt * 64 + j0) = pv;
    }
    __syncthreads();

    // ======== Epilogue: reduce vv || load w2/v_w1 ========
    if (tid < 64) {
        float acc = 0.f;
        #pragma unroll 8
        for (int q = 0; q < 32; q++) acc += pp2[q * 64 + tid];
        vv[tid] = acc;
    } else if (tid >= 256) {
        int u = tid - 256;
        for (int i = u; i < 1024; i += 256) {
            ((float4*)w2s)[i]  = ((const float4*)w2_g)[i];
            ((float4*)vw1s)[i] = ((const float4*)v_w1)[i];
        }
    }
    __syncthreads();
    if (tid < 64) {
        float acc = 0.f;
        #pragma unroll 4
        for (int k = 0; k < 64; k++) acc += vv[k] * w2s[k * 64 + tid];
        feat[tid] = fmaxf(acc, 0.f);
    }
    __syncthreads();
    if (tid < 64) {
        float acc = v_b1[tid];
        #pragma unroll 4
        for (int k = 0; k < 64; k++) acc += feat[k] * vw1s[k * 64 + tid];
        float g = fmaxf(acc, 0.f);
        float p = g * v_w2[tid];
        #pragma unroll
        for (int o = 16; o; o >>= 1) p += __shfl_xor_sync(~0u, p, o);
        if ((tid & 31) == 0) part[tid >> 5] = p;
    }
    __syncthreads();
    if (tid == 0) out[b] = part[0] + part[1] + v_b2[0];
}

extern "C" void kernel_launch(void* const* d_in, const int* in_sizes, int n_in,
                              void* d_out, int out_size) {
    const float* state = (const float*)d_in[0];
    const float* t_w1  = (const float*)d_in[1];
    const float* t_b1  = (const float*)d_in[2];
    const float* t_w2  = (const float*)d_in[3];
    const float* t_b2  = (const float*)d_in[4];
    const float* w_a   = (const float*)d_in[5];
    const float* w1    = (const float*)d_in[6];
    const float* w2    = (const float*)d_in[7];
    const float* v_w1  = (const float*)d_in[8];
    const float* v_b1  = (const float*)d_in[9];
    const float* v_w2  = (const float*)d_in[10];
    const float* v_b2  = (const float*)d_in[11];
    float* out = (float*)d_out;

    const int smem_bytes = SMEM_FLOATS * sizeof(float);
    cudaFuncSetAttribute(value_net_kernel,
                         cudaFuncAttributeMaxDynamicSharedMemorySize, smem_bytes);
    value_net_kernel<<<BATCH, NT, smem_bytes>>>(
        state, t_w1, t_b1, t_w2, t_b2, w_a, w1, w2, v_w1, v_b1, v_w2, v_b2, out);
}

// round 17
// speedup vs baseline: 1.6880x; 1.0054x over previous
#include <cuda_runtime.h>

#define BATCH    8192
#define NT       512

// ---- SMEM layout (floats) ---- (R16 exact; H1 region now truly unused)
#define OFF_XS   0
#define OFF_W    5056
#define OFF_A    9856
#define OFF_Z    19556
#define OFF_SML  25764
#define SMEM_FLOATS (OFF_SML + 464)

typedef unsigned long long u64;

__device__ __forceinline__ u64 pk2(float s) {
    u64 r; asm("mov.b64 %0, {%1, %1};" : "=l"(r) : "f"(s)); return r;
}
__device__ __forceinline__ void fma2(u64& c, u64 a, u64 b) {
    asm("fma.rn.f32x2 %0, %1, %2, %3;" : "=l"(c) : "l"(a), "l"(b), "l"(c));
}
__device__ __forceinline__ float2 upk(u64 v) {
    float2 f; asm("mov.b64 {%0, %1}, %2;" : "=f"(f.x), "=f"(f.y) : "l"(v)); return f;
}

__global__ __launch_bounds__(NT, 2)
void value_net_kernel(const float* __restrict__ state,
                      const float* __restrict__ t_w1, const float* __restrict__ t_b1,
                      const float* __restrict__ t_w2, const float* __restrict__ t_b2,
                      const float* __restrict__ w_a_g, const float* __restrict__ w1_g,
                      const float* __restrict__ w2_g,  const float* __restrict__ v_w1,
                      const float* __restrict__ v_b1,  const float* __restrict__ v_w2,
                      const float* __restrict__ v_b2,  float* __restrict__ out)
{
    extern __shared__ float sm[];
    float* Xs   = sm + OFF_XS;          // stride 52
    float* W    = sm + OFF_W;           // stride 100
    float* pp2  = sm + OFF_A - 2048;    // [32][64] vv partials
    float* A    = sm + OFF_A;           // stride 100 (normalized softmax)
    float* wa52 = sm + OFF_A;           // stride 52 (early)
    float* w1s  = sm + OFF_A + 2496;    // [48][64] (early)
    float* vw1s = sm + OFF_A + 104;     // [64][64] (epilogue)
    float* Z    = sm + OFF_Z;           // stride 64
    float* w2s  = sm + OFF_Z;           // [64][64] (epilogue)
    float* h50  = sm + OFF_SML;
    float* vv   = sm + OFF_SML + 320;
    float* feat = sm + OFF_SML + 384;
    float* part = sm + OFF_SML + 448;

    const int tid = threadIdx.x;
    const int b   = blockIdx.x;
    const float* st = state + (size_t)b * 96 * 64;
    const float4 z4i = make_float4(0.f, 0.f, 0.f, 0.f);

    // ======== R0: loads + MLP stage 1 ========
    if (tid < 50) {
        float acc = t_b1[tid];
        #pragma unroll
        for (int k = 0; k < 16; k++) acc += st[k] * t_w1[k * 50 + tid];
        h50[tid] = fmaxf(acc, 0.f);
    }
    for (int t = tid; t < 2496; t += NT) {
        if (t < 1152) {
            int r = t / 12, c = t % 12;
            *(float4*)(Xs + (r + 1) * 52 + c * 4) =
                *(const float4*)(st + r * 64 + 16 + c * 4);
        } else if (t < 1728) {
            int u = t - 1152; int r = u / 12, c = u % 12;
            *(float4*)(wa52 + r * 52 + c * 4) = ((const float4*)w_a_g)[u];
        } else {
            int u = t - 1728;
            ((float4*)w1s)[u] = ((const float4*)w1_g)[u];
        }
    }
    __syncthreads();

    // ======== R0b: Z rows 1..96 (256 jobs, 6-row) + W m=4..99 (192 jobs)
    //          || tail 448+: MLP2 -> W m0..3, Z row 0 ========
    if (tid < 448) {
        if (tid < 256) {                     // Z: 6-row x 4-col, f32x2
            int n0 = 1 + (tid >> 4) * 6, j0 = (tid & 15) * 4;
            u64 acc[6][2] = {};
            #pragma unroll 3
            for (int k = 0; k < 48; k += 4) {
                ulonglong2 w0 = *(const ulonglong2*)(w1s + (k + 0) * 64 + j0);
                ulonglong2 w1 = *(const ulonglong2*)(w1s + (k + 1) * 64 + j0);
                ulonglong2 w2 = *(const ulonglong2*)(w1s + (k + 2) * 64 + j0);
                ulonglong2 w3 = *(const ulonglong2*)(w1s + (k + 3) * 64 + j0);
                #pragma unroll
                for (int r = 0; r < 6; r++) {
                    float4 xv = *(const float4*)(Xs + (n0 + r) * 52 + k);
                    u64 s0 = pk2(xv.x), s1 = pk2(xv.y), s2 = pk2(xv.z), s3 = pk2(xv.w);
                    fma2(acc[r][0], s0, w0.x); fma2(acc[r][1], s0, w0.y);
                    fma2(acc[r][0], s1, w1.x); fma2(acc[r][1], s1, w1.y);
                    fma2(acc[r][0], s2, w2.x); fma2(acc[r][1], s2, w2.y);
                    fma2(acc[r][0], s3, w3.x); fma2(acc[r][1], s3, w3.y);
                }
            }
            #pragma unroll
            for (int r = 0; r < 6; r++)
                *(ulonglong2*)(Z + (n0 + r) * 64 + j0) = make_ulonglong2(acc[r][0], acc[r][1]);
        } else {                             // W rows k0+8c, cols m0..m0+3
            int u = tid - 256;
            int k0 = u & 7, m0 = 4 + (u >> 3) * 4;
            float4 acc[6] = {z4i, z4i, z4i, z4i, z4i, z4i};
            #pragma unroll 3
            for (int j = 0; j < 48; j += 4) {
                float4 x0 = *(const float4*)(Xs + (m0 + 0) * 52 + j);
                float4 x1 = *(const float4*)(Xs + (m0 + 1) * 52 + j);
                float4 x2 = *(const float4*)(Xs + (m0 + 2) * 52 + j);
                float4 x3 = *(const float4*)(Xs + (m0 + 3) * 52 + j);
                #pragma unroll
                for (int c = 0; c < 6; c++) {
                    float4 w = *(const float4*)(wa52 + (k0 + 8 * c) * 52 + j);
                    acc[c].x += w.x*x0.x + w.y*x0.y + w.z*x0.z + w.w*x0.w;
                    acc[c].y += w.x*x1.x + w.y*x1.y + w.z*x1.z + w.w*x1.w;
                    acc[c].z += w.x*x2.x + w.y*x2.y + w.z*x2.z + w.w*x2.w;
                    acc[c].w += w.x*x3.x + w.y*x3.y + w.z*x3.z + w.w*x3.w;
                }
            }
            #pragma unroll
            for (int c = 0; c < 6; c++)
                *(float4*)(W + (k0 + 8 * c) * 100 + m0) = acc[c];
        }
    } else {
        int j = tid - 448;
        if (j < 48) {                        // MLP stage 2 -> Xs row 0
            float acc = t_b2[j];
            #pragma unroll 5
            for (int k = 0; k < 50; k++) acc += h50[k] * t_w2[k * 48 + j];
            Xs[j] = fmaxf(acc, 0.f);
        }
        asm volatile("bar.sync 1, 64;" ::: "memory");
        if (j < 12) {                        // W rows j+12c, cols 0..3
            float4 acc[4] = {z4i, z4i, z4i, z4i};
            #pragma unroll 3
            for (int jj = 0; jj < 48; jj += 4) {
                float4 x0 = *(const float4*)(Xs + jj);
                float4 x1 = *(const float4*)(Xs + 52 + jj);
                float4 x2 = *(const float4*)(Xs + 104 + jj);
                float4 x3 = *(const float4*)(Xs + 156 + jj);
                #pragma unroll
                for (int c = 0; c < 4; c++) {
                    float4 w = *(const float4*)(wa52 + (j + 12 * c) * 52 + jj);
                    acc[c].x += w.x*x0.x + w.y*x0.y + w.z*x0.z + w.w*x0.w;
                    acc[c].y += w.x*x1.x + w.y*x1.y + w.z*x1.z + w.w*x1.w;
                    acc[c].z += w.x*x2.x + w.y*x2.y + w.z*x2.z + w.w*x2.w;
                    acc[c].w += w.x*x3.x + w.y*x3.y + w.z*x3.z + w.w*x3.w;
                }
            }
            #pragma unroll
            for (int c = 0; c < 4; c++)
                *(float4*)(W + (j + 12 * c) * 100) = acc[c];
        } else if (j < 28) {                 // Z row 0
            int j0 = (j - 12) * 4;
            float4 a = z4i;
            #pragma unroll 4
            for (int k = 0; k < 48; k++) {
                float4 w4 = *(const float4*)(w1s + k * 64 + j0);
                a.x += Xs[k]*w4.x; a.y += Xs[k]*w4.y; a.z += Xs[k]*w4.z; a.w += Xs[k]*w4.w;
            }
            *(float4*)(Z + j0) = a;
        }
    }
    __syncthreads();

    // ======== Scores + fused softmax: A = softmax(X @ W), 16 warps x 6 rows ========
    {
        int warp = tid >> 5, lane = tid & 31;
        int m0 = ((lane < 25) ? lane : 24) * 4;
        int n0 = warp * 6;
        u64 acc[6][2] = {};
        #pragma unroll 3
        for (int k = 0; k < 48; k += 4) {
            ulonglong2 w0 = *(const ulonglong2*)(W + (k + 0) * 100 + m0);
            ulonglong2 w1 = *(const ulonglong2*)(W + (k + 1) * 100 + m0);
            ulonglong2 w2 = *(const ulonglong2*)(W + (k + 2) * 100 + m0);
            ulonglong2 w3 = *(const ulonglong2*)(W + (k + 3) * 100 + m0);
            #pragma unroll
            for (int r = 0; r < 6; r++) {
                float4 xv = *(const float4*)(Xs + (n0 + r) * 52 + k);
                u64 s0 = pk2(xv.x), s1 = pk2(xv.y), s2 = pk2(xv.z), s3 = pk2(xv.w);
                fma2(acc[r][0], s0, w0.x); fma2(acc[r][1], s0, w0.y);
                fma2(acc[r][0], s1, w1.x); fma2(acc[r][1], s1, w1.y);
                fma2(acc[r][0], s2, w2.x); fma2(acc[r][1], s2, w2.y);
                fma2(acc[r][0], s3, w3.x); fma2(acc[r][1], s3, w3.y);
            }
        }
        float e[6][4];
        float p[6];
        #pragma unroll
        for (int r = 0; r < 6; r++) {
            float2 lo = upk(acc[r][0]), hi = upk(acc[r][1]);
            e[r][0] = __expf(lo.x); e[r][1] = __expf(lo.y);
            e[r][2] = __expf(hi.x); e[r][3] = __expf(hi.y);
            p[r] = (lane < 24) ? (e[r][0] + e[r][1]) + (e[r][2] + e[r][3])
                               : ((lane == 24) ? e[r][0] : 0.f);
        }
        #pragma unroll
        for (int o = 16; o; o >>= 1) {
            #pragma unroll
            for (int r = 0; r < 6; r++) p[r] += __shfl_xor_sync(~0u, p[r], o);
        }
        if (lane < 25) {
            #pragma unroll
            for (int r = 0; r < 6; r++) {
                float iv = 1.f / p[r];
                *(float4*)(A + (n0 + r) * 100 + m0) =
                    make_float4(e[r][0] * iv, e[r][1] * iv, e[r][2] * iv, e[r][3] * iv);
            }
        }
        if (warp == 15) {                    // row 96
            u64 b0 = 0, b1 = 0;
            #pragma unroll 3
            for (int k = 0; k < 48; k += 4) {
                ulonglong2 w0 = *(const ulonglong2*)(W + (k + 0) * 100 + m0);
                ulonglong2 w1 = *(const ulonglong2*)(W + (k + 1) * 100 + m0);
                ulonglong2 w2 = *(const ulonglong2*)(W + (k + 2) * 100 + m0);
                ulonglong2 w3 = *(const ulonglong2*)(W + (k + 3) * 100 + m0);
                float4 xv = *(const float4*)(Xs + 96 * 52 + k);
                u64 s0 = pk2(xv.x), s1 = pk2(xv.y), s2 = pk2(xv.z), s3 = pk2(xv.w);
                fma2(b0, s0, w0.x); fma2(b1, s0, w0.y);
                fma2(b0, s1, w1.x); fma2(b1, s1, w1.y);
                fma2(b0, s2, w2.x); fma2(b1, s2, w2.y);
                fma2(b0, s3, w3.x); fma2(b1, s3, w3.y);
            }
            float2 lo = upk(b0), hi = upk(b1);
            float e0 = __expf(lo.x), e1 = __expf(lo.y), e2 = __expf(hi.x), e3 = __expf(hi.y);
            float q = (lane < 24) ? (e0 + e1) + (e2 + e3) : ((lane == 24) ? e0 : 0.f);
            #pragma unroll
            for (int o = 16; o; o >>= 1) q += __shfl_xor_sync(~0u, q, o);
            if (lane < 25) {
                float iv = 1.f / q;
                *(float4*)(A + 96 * 100 + m0) =
                    make_float4(e0 * iv, e1 * iv, e2 * iv, e3 * iv);
            }
        }
    }
    __syncthreads();

    // ======== h1 = relu(A @ Z) -> vv partials only (H1 stores DELETED: dead code) ========
    {
        int nt = tid >> 4, j0 = (tid & 15) * 4;
        int n0 = nt * 3;
        bool last = (nt == 31);
        u64 c0[2] = {}, c1[2] = {}, c2[2] = {}, c3[2] = {};
        for (int m = 0; m < 96; m += 4) {
            ulonglong2 z0 = *(const ulonglong2*)(Z + (m + 0) * 64 + j0);
            ulonglong2 z1 = *(const ulonglong2*)(Z + (m + 1) * 64 + j0);
            ulonglong2 z2 = *(const ulonglong2*)(Z + (m + 2) * 64 + j0);
            ulonglong2 z3 = *(const ulonglong2*)(Z + (m + 3) * 64 + j0);
            float4 a0 = *(const float4*)(A + (n0 + 0) * 100 + m);
            float4 a1 = *(const float4*)(A + (n0 + 1) * 100 + m);
            float4 a2 = *(const float4*)(A + (n0 + 2) * 100 + m);
            u64 p;
            p = pk2(a0.x); fma2(c0[0], p, z0.x); fma2(c0[1], p, z0.y);
            p = pk2(a0.y); fma2(c0[0], p, z1.x); fma2(c0[1], p, z1.y);
            p = pk2(a0.z); fma2(c0[0], p, z2.x); fma2(c0[1], p, z2.y);
            p = pk2(a0.w); fma2(c0[0], p, z3.x); fma2(c0[1], p, z3.y);
            p = pk2(a1.x); fma2(c1[0], p, z0.x); fma2(c1[1], p, z0.y);
            p = pk2(a1.y); fma2(c1[0], p, z1.x); fma2(c1[1], p, z1.y);
            p = pk2(a1.z); fma2(c1[0], p, z2.x); fma2(c1[1], p, z2.y);
            p = pk2(a1.w); fma2(c1[0], p, z3.x); fma2(c1[1], p, z3.y);
            p = pk2(a2.x); fma2(c2[0], p, z0.x); fma2(c2[1], p, z0.y);
            p = pk2(a2.y); fma2(c2[0], p, z1.x); fma2(c2[1], p, z1.y);
            p = pk2(a2.z); fma2(c2[0], p, z2.x); fma2(c2[1], p, z2.y);
            p = pk2(a2.w); fma2(c2[0], p, z3.x); fma2(c2[1], p, z3.y);
            if (last) {
                float4 a3 = *(const float4*)(A + 96 * 100 + m);
                p = pk2(a3.x); fma2(c3[0], p, z0.x); fma2(c3[1], p, z0.y);
                p = pk2(a3.y); fma2(c3[0], p, z1.x); fma2(c3[1], p, z1.y);
                p = pk2(a3.z); fma2(c3[0], p, z2.x); fma2(c3[1], p, z2.y);
                p = pk2(a3.w); fma2(c3[0], p, z3.x); fma2(c3[1], p, z3.y);
            }
        }
        {   // tail m = 96
            ulonglong2 zt = *(const ulonglong2*)(Z + 96 * 64 + j0);
            u64 p;
            p = pk2(A[(n0 + 0) * 100 + 96]); fma2(c0[0], p, zt.x); fma2(c0[1], p, zt.y);
            p = pk2(A[(n0 + 1) * 100 + 96]); fma2(c1[0], p, zt.x); fma2(c1[1], p, zt.y);
            p = pk2(A[(n0 + 2) * 100 + 96]); fma2(c2[0], p, zt.x); fma2(c2[1], p, zt.y);
            if (last) { p = pk2(A[96 * 100 + 96]); fma2(c3[0], p, zt.x); fma2(c3[1], p, zt.y); }
        }
        float2 l0 = upk(c0[0]), h0 = upk(c0[1]);
        float2 l1 = upk(c1[0]), h1v = upk(c1[1]);
        float2 l2 = upk(c2[0]), h2v = upk(c2[1]);
        float4 v0 = make_float4(fmaxf(l0.x,0.f), fmaxf(l0.y,0.f), fmaxf(h0.x,0.f), fmaxf(h0.y,0.f));
        float4 v1 = make_float4(fmaxf(l1.x,0.f), fmaxf(l1.y,0.f), fmaxf(h1v.x,0.f), fmaxf(h1v.y,0.f));
        float4 v2 = make_float4(fmaxf(l2.x,0.f), fmaxf(l2.y,0.f), fmaxf(h2v.x,0.f), fmaxf(h2v.y,0.f));
        float pa0 = A[n0 + 0], pa1 = A[n0 + 1], pa2 = A[n0 + 2];
        float4 pv;
        pv.x = pa0 * v0.x + pa1 * v1.x + pa2 * v2.x;
        pv.y = pa0 * v0.y + pa1 * v1.y + pa2 * v2.y;
        pv.z = pa0 * v0.z + pa1 * v1.z + pa2 * v2.z;
        pv.w = pa0 * v0.w + pa1 * v1.w + pa2 * v2.w;
        if (last) {
            float2 l3 = upk(c3[0]), h3 = upk(c3[1]);
            float4 v3 = make_float4(fmaxf(l3.x,0.f), fmaxf(l3.y,0.f), fmaxf(h3.x,0.f), fmaxf(h3.y,0.f));
            float pa3 = A[96];
            pv.x += pa3 * v3.x; pv.y += pa3 * v3.y; pv.z += pa3 * v3.z; pv.w += pa3 * v3.w;
        }
        *(float4*)(pp2 + nt * 64 + j0) = pv;
    }
    __syncthreads();

    // ======== Epilogue: reduce vv || load w2/v_w1 ========
    if (tid < 64) {
        float acc = 0.f;
        #pragma unroll 8
        for (int q = 0; q < 32; q++) acc += pp2[q * 64 + tid];
        vv[tid] = acc;
    } else if (tid >= 256) {
        int u = tid - 256;
        for (int i = u; i < 1024; i += 256) {
            ((float4*)w2s)[i]  = ((const float4*)w2_g)[i];
            ((float4*)vw1s)[i] = ((const float4*)v_w1)[i];
        }
    }
    __syncthreads();
    if (tid < 64) {
        float acc = 0.f;
        #pragma unroll 4
        for (int k = 0; k < 64; k++) acc += vv[k] * w2s[k * 64 + tid];
        feat[tid] = fmaxf(acc, 0.f);
    }
    __syncthreads();
    if (tid < 64) {
        float acc = v_b1[tid];
        #pragma unroll 4
        for (int k = 0; k < 64; k++) acc += feat[k] * vw1s[k * 64 + tid];
        float g = fmaxf(acc, 0.f);
        float p = g * v_w2[tid];
        #pragma unroll
        for (int o = 16; o; o >>= 1) p += __shfl_xor_sync(~0u, p, o);
        if ((tid & 31) == 0) part[tid >> 5] = p;
    }
    __syncthreads();
    if (tid == 0) out[b] = part[0] + part[1] + v_b2[0];
}

extern "C" void kernel_launch(void* const* d_in, const int* in_sizes, int n_in,
                              void* d_out, int out_size) {
    const float* state = (const float*)d_in[0];
    const float* t_w1  = (const float*)d_in[1];
    const float* t_b1  = (const float*)d_in[2];
    const float* t_w2  = (const float*)d_in[3];
    const float* t_b2  = (const float*)d_in[4];
    const float* w_a   = (const float*)d_in[5];
    const float* w1    = (const float*)d_in[6];
    const float* w2    = (const float*)d_in[7];
    const float* v_w1  = (const float*)d_in[8];
    const float* v_b1  = (const float*)d_in[9];
    const float* v_w2  = (const float*)d_in[10];
    const float* v_b2  = (const float*)d_in[11];
    float* out = (float*)d_out;

    const int smem_bytes = SMEM_FLOATS * sizeof(float);
    cudaFuncSetAttribute(value_net_kernel,
                         cudaFuncAttributeMaxDynamicSharedMemorySize, smem_bytes);
    value_net_kernel<<<BATCH, NT, smem_bytes>>>(
        state, t_w1, t_b1, t_w2, t_b2, w_a, w1, w2, v_w1, v_b1, v_w2, v_b2, out);
}